// round 1
// baseline (speedup 1.0000x reference)
#include <cuda_runtime.h>
#include <cstdint>

// Shapes fixed by the problem: x (64,64,128,128) fp32, coeff (64,32) fp32, out (64,64) fp32.
#define N_ELEM   67108864   // 64*64*128*128
#define N_F4     16777216   // N_ELEM/4
#define N_PLANES 4096       // N*C
#define HW       16384
#define HW4      4096       // HW/4
#define BINS     32

// scratch: [0]=encoded min, [1]=encoded max (monotone uint encoding of float)
__device__ unsigned g_mm[2];

__device__ __forceinline__ unsigned fenc(float f) {
    unsigned u = __float_as_uint(f);
    return (u & 0x80000000u) ? ~u : (u | 0x80000000u);
}
__device__ __forceinline__ float fdec(unsigned e) {
    return (e & 0x80000000u) ? __uint_as_float(e ^ 0x80000000u)
                             : __uint_as_float(~e);
}

__global__ void init_kernel() {
    g_mm[0] = 0xFFFFFFFFu;  // running min (encoded): start at +max
    g_mm[1] = 0x00000000u;  // running max (encoded): start at -max
}

__global__ void __launch_bounds__(256) minmax_kernel(const float4* __restrict__ x) {
    float lo =  3.402823466e38f;
    float hi = -3.402823466e38f;
    int stride = gridDim.x * blockDim.x;
    for (int i = blockIdx.x * blockDim.x + threadIdx.x; i < N_F4; i += stride) {
        float4 v = x[i];
        lo = fminf(lo, fminf(fminf(v.x, v.y), fminf(v.z, v.w)));
        hi = fmaxf(hi, fmaxf(fmaxf(v.x, v.y), fmaxf(v.z, v.w)));
    }
    // warp reduce
    #pragma unroll
    for (int o = 16; o; o >>= 1) {
        lo = fminf(lo, __shfl_xor_sync(0xFFFFFFFFu, lo, o));
        hi = fmaxf(hi, __shfl_xor_sync(0xFFFFFFFFu, hi, o));
    }
    __shared__ float s_lo[8], s_hi[8];
    int t = threadIdx.x;
    if ((t & 31) == 0) { s_lo[t >> 5] = lo; s_hi[t >> 5] = hi; }
    __syncthreads();
    if (t < 32) {
        lo = (t < 8) ? s_lo[t] :  3.402823466e38f;
        hi = (t < 8) ? s_hi[t] : -3.402823466e38f;
        #pragma unroll
        for (int o = 4; o; o >>= 1) {
            lo = fminf(lo, __shfl_xor_sync(0xFFFFFFFFu, lo, o));
            hi = fmaxf(hi, __shfl_xor_sync(0xFFFFFFFFu, hi, o));
        }
        if (t == 0) {
            atomicMin(&g_mm[0], fenc(lo));
            atomicMax(&g_mm[1], fenc(hi));
        }
    }
}

__global__ void __launch_bounds__(256) hpool_kernel(const float4* __restrict__ x,
                                                    const float* __restrict__ coeff,
                                                    float* __restrict__ out) {
    __shared__ float s_tau[BINS + 1];
    __shared__ float s_cf[BINS];
    __shared__ float s_red[8];

    // Reverse plane order: pass 1 streamed forward, its tail is L2-resident.
    int plane = (N_PLANES - 1) - (int)blockIdx.x;
    int c = plane & 63;

    float xmin = fdec(g_mm[0]);
    float xmax = fdec(g_mm[1]);
    // Match jnp.linspace fp32 arithmetic: delta=(stop-start)/div; tau[i]=start + i*delta
    // (separate rn mul + rn add, no fma contraction).
    float delta = __fdiv_rn(__fsub_rn(xmax, xmin), 32.0f);
    float inv_delta = __frcp_rn(delta);

    int t = threadIdx.x;
    if (t <= BINS) s_tau[t] = __fadd_rn(xmin, __fmul_rn((float)t, delta));
    if (t < BINS)  s_cf[t]  = coeff[c * BINS + t];
    __syncthreads();

    const float4* px = x + (size_t)plane * HW4;
    float acc = 0.0f;

    #pragma unroll
    for (int it = 0; it < HW4 / 256; it++) {
        float4 v = px[t + it * 256];
        float vv[4] = {v.x, v.y, v.z, v.w};
        #pragma unroll
        for (int j = 0; j < 4; j++) {
            float xv = vv[j];
            // approximate bin, then exact correction against tau (== searchsorted right - 1)
            float f = (xv - xmin) * inv_delta;
            int i0 = (int)f;
            i0 = min(max(i0, 0), BINS - 1);
            if (i0 < BINS - 1 && xv >= s_tau[i0 + 1]) i0++;
            else if (i0 > 0 && xv < s_tau[i0])        i0--;
            // tanh(x) = 1 - 2/(exp2(2x*log2e)+1)  (2 MUFU + 3 FMA, ~few-ulp accurate)
            float e, r;
            asm("ex2.approx.f32 %0, %1;" : "=f"(e) : "f"(xv * 2.88539004f));
            asm("rcp.approx.f32 %0, %1;" : "=f"(r) : "f"(e + 1.0f));
            float th = fmaf(-2.0f, r, 1.0f);
            acc = fmaf(th, s_cf[i0], acc);
        }
    }

    // block reduce (8 warps)
    #pragma unroll
    for (int o = 16; o; o >>= 1) acc += __shfl_xor_sync(0xFFFFFFFFu, acc, o);
    if ((t & 31) == 0) s_red[t >> 5] = acc;
    __syncthreads();
    if (t < 32) {
        float a = (t < 8) ? s_red[t] : 0.0f;
        #pragma unroll
        for (int o = 4; o; o >>= 1) a += __shfl_xor_sync(0xFFFFFFFFu, a, o);
        if (t == 0) out[plane] = a;
    }
}

extern "C" void kernel_launch(void* const* d_in, const int* in_sizes, int n_in,
                              void* d_out, int out_size) {
    const float4* x     = (const float4*)d_in[0];
    const float*  coeff = (const float*)d_in[1];
    float*        out   = (float*)d_out;

    init_kernel<<<1, 1>>>();
    minmax_kernel<<<1184, 256>>>(x);
    hpool_kernel<<<N_PLANES, 256>>>(x, coeff, out);
}